// round 2
// baseline (speedup 1.0000x reference)
#include <cuda_runtime.h>
#include <cuda_bf16.h>

#define NATOM 100000
#define MNBR  12
#define AF    64
#define BF    41
#define TWOA  128
#define NM    (NATOM*MNBR)          // 1200000
#define NMF   ((double)NM)
#define NF    ((double)NATOM)
#define EPSBN 1e-5

// ---------------- scratch (device globals; no allocations) ----------------
__device__ float  d_SW[(size_t)NATOM*TWOA];      // atom @ W[0:64]   (51.2 MB)
__device__ float  d_PW[(size_t)NATOM*TWOA];      // atom @ W[64:128] (51.2 MB)
__device__ float  d_gated[(size_t)NM*TWOA];      // staged gated     (614 MB)
__device__ float  d_summed[(size_t)NATOM*AF];    // (25.6 MB)
__device__ double d_s1[TWOA], d_q1[TWOA];
__device__ double d_s2[AF],   d_q2[AF];
__device__ float  d_g1[TWOA], d_h1[TWOA];
__device__ float  d_g2[AF],   d_h2[AF];

// ---------------- math helpers ----------------
__device__ __forceinline__ float sigmoidf_(float x) {
    return __fdividef(1.0f, 1.0f + __expf(-x));
}
__device__ __forceinline__ float softplusf_(float x) {
    // stable: max(x,0) + log(1+exp(-|x|)); abs err ~6e-8, fine here
    float e = __expf(-fabsf(x));
    return fmaxf(x, 0.0f) + __logf(1.0f + e);
}

// ---------------- zero stats ----------------
__global__ void kZero() {
    int t = threadIdx.x;
    if (t < TWOA) { d_s1[t] = 0.0; d_q1[t] = 0.0; }
    if (t < AF)   { d_s2[t] = 0.0; d_q2[t] = 0.0; }
}

// ---------------- kA: SW = atom@W[0:64,:], PW = atom@W[64:128,:] ----------------
// block: 256 threads, each owns one output column (t<128 -> SW col t, else PW col t-128)
// tile: 128 atoms per block
__global__ void __launch_bounds__(256) kA(const float* __restrict__ atom,
                                          const float* __restrict__ W) {
    __shared__ float at[64][132];   // transposed atom tile [k][a], padded
    int t = threadIdx.x;
    int aBase = blockIdx.x * 128;
    int aCount = NATOM - aBase; if (aCount > 128) aCount = 128;

    // weight column in registers
    float w[64];
    const float* wp = (t < 128) ? (W + t) : (W + 64 * TWOA + (t - 128));
    #pragma unroll
    for (int k = 0; k < 64; k++) w[k] = wp[k * TWOA];

    // load atoms transposed
    for (int idx = t; idx < 128 * 64; idx += 256) {
        int a = idx >> 6, k = idx & 63;
        at[k][a] = (a < aCount) ? atom[(size_t)(aBase + a) * AF + k] : 0.0f;
    }
    __syncthreads();

    float* dst = (t < 128) ? d_SW : d_PW;
    int j = (t < 128) ? t : (t - 128);

    for (int c = 0; c < 16; c++) {
        int a0 = c * 8;
        float acc[8];
        #pragma unroll
        for (int i = 0; i < 8; i++) acc[i] = 0.0f;
        #pragma unroll
        for (int k = 0; k < 64; k++) {
            float4 x0 = *(float4*)&at[k][a0];
            float4 x1 = *(float4*)&at[k][a0 + 4];
            float xr[8] = {x0.x, x0.y, x0.z, x0.w, x1.x, x1.y, x1.z, x1.w};
            #pragma unroll
            for (int i = 0; i < 8; i++) acc[i] += xr[i] * w[k];
        }
        #pragma unroll
        for (int i = 0; i < 8; i++) {
            int a = a0 + i;
            if (a < aCount) dst[(size_t)(aBase + a) * TWOA + j] = acc[i];
        }
    }
}

// ---------------- kB: gated = bond@W3 + SW[n] + PW[idx] + b; stage + stats ----------------
// block: 256 threads, 64 rows x 128 cols; thread: 8 rows x 4 cols
__global__ void __launch_bounds__(256) kB(const float* __restrict__ bond,
                                          const int*   __restrict__ nidx,
                                          const float* __restrict__ W,
                                          const float* __restrict__ bias) {
    __shared__ float Ws[BF][TWOA];     // 20992 B
    __shared__ float bT[BF][68];       // 11152 B (transposed bond tile, padded)
    __shared__ float redS[8][TWOA];    // 4096 B
    __shared__ float redQ[8][TWOA];    // 4096 B

    int t = threadIdx.x;
    int rowBase = blockIdx.x * 64;

    for (int idx = t; idx < BF * TWOA; idx += 256)
        Ws[idx / TWOA][idx & (TWOA - 1)] = W[TWOA * TWOA + idx];
    const float* bsrc = bond + (size_t)rowBase * BF;
    for (int idx = t; idx < 64 * BF; idx += 256)
        bT[idx % BF][idx / BF] = bsrc[idx];
    __syncthreads();

    int c0 = (t & 31) * 4;
    int r0 = (t >> 5) * 8;

    float acc[8][4];
    #pragma unroll
    for (int i = 0; i < 8; i++)
        #pragma unroll
        for (int u = 0; u < 4; u++) acc[i][u] = 0.0f;

    #pragma unroll
    for (int k = 0; k < BF; k++) {
        float4 wv = *(float4*)&Ws[k][c0];
        float4 b0 = *(float4*)&bT[k][r0];
        float4 b1 = *(float4*)&bT[k][r0 + 4];
        float br[8] = {b0.x, b0.y, b0.z, b0.w, b1.x, b1.y, b1.z, b1.w};
        float wr[4] = {wv.x, wv.y, wv.z, wv.w};
        #pragma unroll
        for (int i = 0; i < 8; i++)
            #pragma unroll
            for (int u = 0; u < 4; u++) acc[i][u] += br[i] * wr[u];
    }

    float4 bv = *(const float4*)&bias[c0];
    float ls[4] = {0, 0, 0, 0}, lq[4] = {0, 0, 0, 0};

    #pragma unroll
    for (int i = 0; i < 8; i++) {
        int rr = rowBase + r0 + i;
        int n  = rr / 12;
        int gi = nidx[rr];
        float4 sw = *(float4*)&d_SW[(size_t)n  * TWOA + c0];
        float4 pw = *(float4*)&d_PW[(size_t)gi * TWOA + c0];
        float4 g;
        g.x = acc[i][0] + sw.x + pw.x + bv.x;
        g.y = acc[i][1] + sw.y + pw.y + bv.y;
        g.z = acc[i][2] + sw.z + pw.z + bv.z;
        g.w = acc[i][3] + sw.w + pw.w + bv.w;
        *(float4*)&d_gated[(size_t)rr * TWOA + c0] = g;
        ls[0] += g.x; lq[0] += g.x * g.x;
        ls[1] += g.y; lq[1] += g.y * g.y;
        ls[2] += g.z; lq[2] += g.z * g.z;
        ls[3] += g.w; lq[3] += g.w * g.w;
    }

    int wrp = t >> 5;
    #pragma unroll
    for (int u = 0; u < 4; u++) { redS[wrp][c0 + u] = ls[u]; redQ[wrp][c0 + u] = lq[u]; }
    __syncthreads();
    if (t < TWOA) {
        float s = 0.0f, q = 0.0f;
        #pragma unroll
        for (int w2 = 0; w2 < 8; w2++) { s += redS[w2][t]; q += redQ[w2][t]; }
        atomicAdd(&d_s1[t], (double)s);
        atomicAdd(&d_q1[t], (double)q);
    }
}

// ---------------- fin1 / fin2: fold BN into per-feature affine ----------------
__global__ void fin1(const float* __restrict__ scale, const float* __restrict__ offset) {
    int j = threadIdx.x;   // 128
    double mean = d_s1[j] / NMF;
    double var  = d_q1[j] / NMF - mean * mean;
    float g = scale[j] * (float)(1.0 / sqrt(var + EPSBN));
    d_g1[j] = g;
    d_h1[j] = offset[j] - (float)mean * g;
}
__global__ void fin2(const float* __restrict__ scale, const float* __restrict__ offset) {
    int j = threadIdx.x;   // 64
    double mean = d_s2[j] / NF;
    double var  = d_q2[j] / NF - mean * mean;
    float g = scale[j] * (float)(1.0 / sqrt(var + EPSBN));
    d_g2[j] = g;
    d_h2[j] = offset[j] - (float)mean * g;
}

// ---------------- kC: BN1 affine + sigmoid*softplus + sum over M; BN2 stats ----------------
// block: 256 threads = 8 warps = 8 atoms; lane j owns output cols j and j+32
__global__ void __launch_bounds__(256) kC() {
    __shared__ float rs[8][AF];
    __shared__ float rq[8][AF];
    int t = threadIdx.x;
    int j = t & 31;
    int w = t >> 5;
    int a = blockIdx.x * 8 + w;

    float g1a = d_g1[j],      h1a = d_h1[j];
    float g1b = d_g1[j + 32], h1b = d_h1[j + 32];
    float g1c = d_g1[j + 64], h1c = d_h1[j + 64];
    float g1d = d_g1[j + 96], h1d = d_h1[j + 96];

    float s0 = 0.0f, s1 = 0.0f;
    #pragma unroll
    for (int m = 0; m < MNBR; m++) {
        size_t base = ((size_t)a * MNBR + m) * TWOA;
        float f0 = d_gated[base + j]      * g1a + h1a;
        float f1 = d_gated[base + j + 32] * g1b + h1b;
        float c0 = d_gated[base + j + 64] * g1c + h1c;
        float c1 = d_gated[base + j + 96] * g1d + h1d;
        s0 += sigmoidf_(f0) * softplusf_(c0);
        s1 += sigmoidf_(f1) * softplusf_(c1);
    }
    d_summed[(size_t)a * AF + j]      = s0;
    d_summed[(size_t)a * AF + j + 32] = s1;

    rs[w][j] = s0;       rq[w][j] = s0 * s0;
    rs[w][j + 32] = s1;  rq[w][j + 32] = s1 * s1;
    __syncthreads();
    if (t < AF) {
        float s = 0.0f, q = 0.0f;
        #pragma unroll
        for (int w2 = 0; w2 < 8; w2++) { s += rs[w2][t]; q += rq[w2][t]; }
        atomicAdd(&d_s2[t], (double)s);
        atomicAdd(&d_q2[t], (double)q);
    }
}

// ---------------- kD: out = softplus(atom + BN2(summed)) ----------------
__global__ void __launch_bounds__(256) kD(const float* __restrict__ atom,
                                          float* __restrict__ out) {
    int i = blockIdx.x * 256 + threadIdx.x;      // grid sized exactly N*AF
    int c = i & (AF - 1);
    float y = d_summed[i] * d_g2[c] + d_h2[c];
    out[i] = softplusf_(atom[i] + y);
}

// ---------------- launch ----------------
extern "C" void kernel_launch(void* const* d_in, const int* in_sizes, int n_in,
                              void* d_out, int out_size) {
    const int*   nidx = (const int*)  d_in[0];   // (N, M) int32
    const float* atom = (const float*)d_in[1];   // (N, 64)
    const float* bond = (const float*)d_in[2];   // (N, M, 41)
    const float* W    = (const float*)d_in[3];   // (169, 128)
    const float* bias = (const float*)d_in[4];   // (128,)
    const float* bn1s = (const float*)d_in[5];
    const float* bn1o = (const float*)d_in[6];
    const float* bn2s = (const float*)d_in[7];
    const float* bn2o = (const float*)d_in[8];
    float* out = (float*)d_out;

    kZero<<<1, 128>>>();
    kA<<<(NATOM + 127) / 128, 256>>>(atom, W);
    kB<<<NM / 64, 256>>>(bond, nidx, W, bias);
    fin1<<<1, TWOA>>>(bn1s, bn1o);
    kC<<<NATOM / 8, 256>>>();
    fin2<<<1, AF>>>(bn2s, bn2o);
    kD<<<(NATOM * AF) / 256, 256>>>(atom, out);
}